// round 1
// baseline (speedup 1.0000x reference)
#include <cuda_runtime.h>
#include <cuda_bf16.h>
#include <math.h>

// Shapes are fixed by the reference: B=32, C=512, H=W=64.
#define B_  32
#define C_  512
#define HW_ 4096
#define BC_ (B_ * C_)   // 16384

// Scratch (no device allocation allowed -> __device__ globals)
__device__ float g_d[BC_];    // per-(b,c) max
__device__ float g_e[BC_];    // per-(b,c) mean
__device__ float g_fm[BC_];   // f_max accumulator
__device__ float g_fe[BC_];   // f_mean accumulator

// ---------------------------------------------------------------------------
// Kernel 1: per-(b,c) max & mean over the 4096-element plane.
// One 128-thread block per plane; 8 x float4 per thread (128B / thread).
// Blocks 0..255 additionally zero g_fm / g_fe (required every graph replay).
// ---------------------------------------------------------------------------
__global__ __launch_bounds__(128) void k_pool(const float* __restrict__ x) {
    const int bc  = blockIdx.x;
    const int tid = threadIdx.x;

    const float4* p = reinterpret_cast<const float4*>(x) + (size_t)bc * (HW_ / 4);

    float mx = -INFINITY;
    float sm = 0.0f;
#pragma unroll
    for (int k = 0; k < 8; ++k) {
        float4 v = p[tid + 128 * k];
        mx = fmaxf(mx, fmaxf(fmaxf(v.x, v.y), fmaxf(v.z, v.w)));
        sm += (v.x + v.y) + (v.z + v.w);
    }

    // warp reduce
#pragma unroll
    for (int o = 16; o > 0; o >>= 1) {
        mx = fmaxf(mx, __shfl_xor_sync(0xFFFFFFFFu, mx, o));
        sm += __shfl_xor_sync(0xFFFFFFFFu, sm, o);
    }

    __shared__ float smx[4], ssm[4];
    const int w = tid >> 5, l = tid & 31;
    if (l == 0) { smx[w] = mx; ssm[w] = sm; }
    __syncthreads();
    if (tid == 0) {
        float M = smx[0], S = ssm[0];
#pragma unroll
        for (int i = 1; i < 4; ++i) { M = fmaxf(M, smx[i]); S += ssm[i]; }
        g_d[bc] = M;
        g_e[bc] = S * (1.0f / (float)HW_);
    }

    // zero accumulators (256 blocks x 128 threads cover both arrays)
    if (blockIdx.x < 128) {
        g_fm[blockIdx.x * 128 + tid] = 0.0f;
    } else if (blockIdx.x < 256) {
        g_fe[(blockIdx.x - 128) * 128 + tid] = 0.0f;
    }
}

// ---------------------------------------------------------------------------
// Kernel 2: per-batch softmax-weighted sums.
//   y[i][j] = d_i*d_j + e_i*e_j ; p = softmax_j(y[i]) ;
//   f_max[j] += d_i * p[i][j] ; f_mean[j] += e_i * p[i][j]
// Grid: 32 batches x 8 chunks (64 rows each). Block = 256 threads (8 warps),
// one warp per row; lane l owns columns {l + 32c, c<16} in registers.
// Partials merged via global atomicAdd (spread addresses, low contention).
// ---------------------------------------------------------------------------
__global__ __launch_bounds__(256) void k_softmax() {
    const int b     = blockIdx.x >> 3;
    const int chunk = blockIdx.x & 7;
    const int tid   = threadIdx.x;
    const int lane  = tid & 31;
    const int w     = tid >> 5;

    __shared__ float s_d[C_], s_e[C_];
    for (int i = tid; i < C_; i += 256) {
        s_d[i] = g_d[b * C_ + i];
        s_e[i] = g_e[b * C_ + i];
    }
    __syncthreads();

    float dj[16], ej[16];
#pragma unroll
    for (int c = 0; c < 16; ++c) {
        dj[c] = s_d[lane + 32 * c];
        ej[c] = s_e[lane + 32 * c];
    }

    float fm[16], fe[16];
#pragma unroll
    for (int c = 0; c < 16; ++c) { fm[c] = 0.0f; fe[c] = 0.0f; }

    for (int r = w; r < 64; r += 8) {
        const int i = chunk * 64 + r;
        const float di = s_d[i];
        const float ei = s_e[i];

        float t[16];
        float m = -INFINITY;
#pragma unroll
        for (int c = 0; c < 16; ++c) {
            t[c] = fmaf(di, dj[c], ei * ej[c]);
            m = fmaxf(m, t[c]);
        }
#pragma unroll
        for (int o = 16; o > 0; o >>= 1)
            m = fmaxf(m, __shfl_xor_sync(0xFFFFFFFFu, m, o));

        float s = 0.0f;
#pragma unroll
        for (int c = 0; c < 16; ++c) {
            t[c] = __expf(t[c] - m);
            s += t[c];
        }
#pragma unroll
        for (int o = 16; o > 0; o >>= 1)
            s += __shfl_xor_sync(0xFFFFFFFFu, s, o);

        const float inv = 1.0f / s;
        const float ad = di * inv;
        const float ae = ei * inv;
#pragma unroll
        for (int c = 0; c < 16; ++c) {
            fm[c] = fmaf(ad, t[c], fm[c]);
            fe[c] = fmaf(ae, t[c], fe[c]);
        }
    }

#pragma unroll
    for (int c = 0; c < 16; ++c) {
        atomicAdd(&g_fm[b * C_ + lane + 32 * c], fm[c]);
        atomicAdd(&g_fe[b * C_ + lane + 32 * c], fe[c]);
    }
}

// ---------------------------------------------------------------------------
// Kernel 3: f = alpha*f_max + beta*f_mean, broadcast over the 4096 plane.
// One 256-thread block per (b,c); 4 x float4 stores per thread.
// ---------------------------------------------------------------------------
__global__ __launch_bounds__(256) void k_bcast(const float* __restrict__ alpha,
                                               const float* __restrict__ beta,
                                               float* __restrict__ out) {
    const int bc  = blockIdx.x;
    const int tid = threadIdx.x;

    const float f = alpha[0] * g_fm[bc] + beta[0] * g_fe[bc];
    const float4 v = make_float4(f, f, f, f);

    float4* o = reinterpret_cast<float4*>(out) + (size_t)bc * (HW_ / 4);
#pragma unroll
    for (int k = 0; k < 4; ++k)
        o[tid + 256 * k] = v;
}

extern "C" void kernel_launch(void* const* d_in, const int* in_sizes, int n_in,
                              void* d_out, int out_size) {
    const float* x     = (const float*)d_in[0];
    const float* alpha = (const float*)d_in[1];
    const float* beta  = (const float*)d_in[2];
    float* out = (float*)d_out;

    k_pool<<<BC_, 128>>>(x);
    k_softmax<<<B_ * 8, 256>>>();
    k_bcast<<<BC_, 256>>>(alpha, beta, out);
}